// round 5
// baseline (speedup 1.0000x reference)
#include <cuda_runtime.h>
#include <cuda_bf16.h>
#include <cstdint>
#include <math.h>

#define NQ 128
#define ND 1024
#define DD 256
#define CAT 512
#define MEGA_CTAS 148

// ---------------- device scratch ----------------
__device__ float g_qh[NQ * DD];
__device__ float g_dh[ND * DD];
__device__ float g_qB[NQ * CAT];
__device__ float g_dB[ND * CAT];
__device__ float g_qdeg[NQ];
__device__ float g_ddeg[ND];
__device__ float g_cosw[8192];
__device__ float g_Bq[NQ * DD];
__device__ float g_Bd[ND * DD];
__device__ float g_pmax[256];
__device__ float g_psum[256];
__device__ unsigned g_bar_count = 0;
__device__ volatile unsigned g_bar_gen = 0;

// packed weights: [N][K] bf16, hi and lo parts
#define OFF_QW0 0
#define OFF_DW0 65536
#define OFF_QW1 131072
#define OFF_DW1 262144
#define OFF_W1T 393216
#define OFF_W1B 655360
#define OFF_W2  917504
#define OFF_W3  1048576
#define WPACK_TOTAL 1081344
__device__ __align__(16) __nv_bfloat16 g_wh[WPACK_TOTAL];
__device__ __align__(16) __nv_bfloat16 g_wl[WPACK_TOTAL];

// ---------------- shared helpers ----------------
__device__ __forceinline__ uint32_t smem_u32(const void* p) {
    uint32_t a;
    asm("{ .reg .u64 t; cvta.to.shared.u64 t, %1; cvt.u32.u64 %0, t; }" : "=r"(a) : "l"(p));
    return a;
}

__device__ __forceinline__ void cp16(uint32_t dst, const void* src) {
    asm volatile("cp.async.cg.shared.global [%0], [%1], 16;" :: "r"(dst), "l"(src));
}

__device__ __forceinline__ void mma_bf16(float c[4],
                                         uint32_t a0, uint32_t a1, uint32_t a2, uint32_t a3,
                                         uint32_t b0, uint32_t b1)
{
    asm volatile("mma.sync.aligned.m16n8k16.row.col.f32.bf16.bf16.f32 "
                 "{%0,%1,%2,%3}, {%4,%5,%6,%7}, {%8,%9}, {%0,%1,%2,%3};"
                 : "+f"(c[0]), "+f"(c[1]), "+f"(c[2]), "+f"(c[3])
                 : "r"(a0), "r"(a1), "r"(a2), "r"(a3), "r"(b0), "r"(b1));
}

__device__ __forceinline__ void split_pack(float v0, float v1, uint32_t& hi, uint32_t& lo)
{
    asm("cvt.rn.bf16x2.f32 %0, %1, %2;" : "=r"(hi) : "f"(v1), "f"(v0));
    float h0 = __uint_as_float(hi << 16);
    float h1 = __uint_as_float(hi & 0xffff0000u);
    float r0 = v0 - h0, r1 = v1 - h1;
    asm("cvt.rn.bf16x2.f32 %0, %1, %2;" : "=r"(lo) : "f"(r1), "f"(r0));
}

// grid-wide barrier (all gridDim.x CTAs resident; generation-based, replay-safe)
__device__ __forceinline__ void grid_sync()
{
    __threadfence();
    __syncthreads();
    if (threadIdx.x == 0) {
        unsigned g = g_bar_gen;
        if (atomicAdd(&g_bar_count, 1) == gridDim.x - 1) {
            g_bar_count = 0;
            __threadfence();
            g_bar_gen = g + 1;
        } else {
            while (g_bar_gen == g) { }
            __threadfence();
        }
    }
    __syncthreads();
}

// ---------------- weight pack: transpose + bf16 split ----------------
struct PackJob { const float* src; int K, N, ld; int64_t off; };
struct PackArgs { PackJob j[8]; };

__global__ void pack_kernel(PackArgs pa, __nv_bfloat16* __restrict__ wh,
                            __nv_bfloat16* __restrict__ wl)
{
    __shared__ float tile[32][33];
    const PackJob jb = pa.j[blockIdx.y];
    int ntilesK = jb.K >> 5;
    int ntiles = ntilesK * (jb.N >> 5);
    if ((int)blockIdx.x >= ntiles) return;
    int kt = blockIdx.x % ntilesK, nt = blockIdx.x / ntilesK;
    int tx = threadIdx.x & 31, ty = threadIdx.x >> 5;
    #pragma unroll
    for (int p = 0; p < 4; p++) {
        int row = ty + p * 8;
        tile[row][tx] = jb.src[(size_t)(kt * 32 + row) * jb.ld + nt * 32 + tx];
    }
    __syncthreads();
    #pragma unroll
    for (int p = 0; p < 4; p++) {
        int row = ty + p * 8;
        float v = tile[tx][row];
        __nv_bfloat16 h = __float2bfloat16(v);
        float r = v - __bfloat162float(h);
        size_t o = jb.off + (size_t)(nt * 32 + row) * jb.K + kt * 32 + tx;
        wh[o] = h;
        wl[o] = __float2bfloat16(r);
    }
}

// ---------------- HMMA split-bf16 GEMM, 2-stage cp.async pipeline ----------------
struct GemmJob {
    const float* A;
    const __nv_bfloat16* Bh;
    const __nv_bfloat16* Bl;
    float* C;
    const float* bias;
    int M, N, K, lda, ldc;
};

#define HG_A     0
#define HG_ASTR  288
#define HG_BH    36864
#define HG_BL    46080
#define HG_BSTR  144
#define HG_STAGE 55296
#define HG_SMEM  (2 * HG_STAGE)

__global__ void __launch_bounds__(256)
hgemm_kernel(GemmJob j0, GemmJob j1)
{
    GemmJob jb = (blockIdx.z == 0) ? j0 : j1;
    const int n0 = blockIdx.x * 64;
    const int m0 = blockIdx.y * 128;
    if (n0 >= jb.N || m0 >= jb.M) return;
    extern __shared__ char sm[];
    const uint32_t smb = smem_u32(sm);
    const int t = threadIdx.x, lane = t & 31, wid = t >> 5;
    const int warp_m = wid & 3, warp_n = wid >> 2;
    const int qr = lane >> 2, qk = (lane & 3) * 2;
    float acc[2][4][4] = {};
    const int nchunks = jb.K >> 6;

    auto issue = [&](int kc, int stage) {
        uint32_t base = smb + stage * HG_STAGE;
        {
            int row = t >> 1, half = t & 1;
            const float* src = jb.A + (size_t)(m0 + row) * jb.lda + kc + half * 32;
            uint32_t dst = base + HG_A + row * HG_ASTR + half * 128;
            #pragma unroll
            for (int i = 0; i < 8; i++) cp16(dst + i * 16, src + i * 4);
        }
        #pragma unroll
        for (int p = 0; p < 2; p++) {
            int idx = t + p * 256;
            int row = idx >> 3, c = idx & 7;
            size_t go = (size_t)(n0 + row) * jb.K + kc + c * 8;
            cp16(base + HG_BH + row * HG_BSTR + c * 16, jb.Bh + go);
            cp16(base + HG_BL + row * HG_BSTR + c * 16, jb.Bl + go);
        }
        asm volatile("cp.async.commit_group;");
    };

    issue(0, 0);
    for (int c = 0; c < nchunks; c++) {
        if (c + 1 < nchunks) {
            issue((c + 1) * 64, (c + 1) & 1);
            asm volatile("cp.async.wait_group 1;");
        } else {
            asm volatile("cp.async.wait_group 0;");
        }
        __syncthreads();
        const char* smc = sm + (c & 1) * HG_STAGE;
        #pragma unroll
        for (int kk = 0; kk < 64; kk += 16) {
            uint32_t bh[4][2], bl[4][2];
            #pragma unroll
            for (int f = 0; f < 4; f++) {
                int n = warp_n * 32 + f * 8 + qr;
                const char* bp = smc + n * HG_BSTR + (kk + qk) * 2;
                bh[f][0] = *(const uint32_t*)(bp + HG_BH);
                bh[f][1] = *(const uint32_t*)(bp + HG_BH + 16);
                bl[f][0] = *(const uint32_t*)(bp + HG_BL);
                bl[f][1] = *(const uint32_t*)(bp + HG_BL + 16);
            }
            #pragma unroll
            for (int s = 0; s < 2; s++) {
                int r = warp_m * 32 + s * 16 + qr;
                const char* ap = smc + HG_A + r * HG_ASTR + (kk + qk) * 4;
                float2 a0 = *(const float2*)ap;
                float2 a1 = *(const float2*)(ap + 8 * HG_ASTR);
                float2 a2 = *(const float2*)(ap + 32);
                float2 a3 = *(const float2*)(ap + 8 * HG_ASTR + 32);
                uint32_t ah[4], al[4];
                split_pack(a0.x, a0.y, ah[0], al[0]);
                split_pack(a1.x, a1.y, ah[1], al[1]);
                split_pack(a2.x, a2.y, ah[2], al[2]);
                split_pack(a3.x, a3.y, ah[3], al[3]);
                #pragma unroll
                for (int f = 0; f < 4; f++) {
                    mma_bf16(acc[s][f], ah[0], ah[1], ah[2], ah[3], bh[f][0], bh[f][1]);
                    mma_bf16(acc[s][f], al[0], al[1], al[2], al[3], bh[f][0], bh[f][1]);
                    mma_bf16(acc[s][f], ah[0], ah[1], ah[2], ah[3], bl[f][0], bl[f][1]);
                }
            }
        }
        __syncthreads();
    }
    #pragma unroll
    for (int s = 0; s < 2; s++) {
        int r = m0 + warp_m * 32 + s * 16 + qr;
        #pragma unroll
        for (int f = 0; f < 4; f++) {
            int n = n0 + warp_n * 32 + f * 8 + qk;
            float bs0 = jb.bias ? jb.bias[n] : 0.0f;
            float bs1 = jb.bias ? jb.bias[n + 1] : 0.0f;
            float2 v0 = { acc[s][f][0] + bs0, acc[s][f][1] + bs1 };
            float2 v1 = { acc[s][f][2] + bs0, acc[s][f][3] + bs1 };
            *(float2*)(jb.C + (size_t)r * jb.ldc + n) = v0;
            *(float2*)(jb.C + (size_t)(r + 8) * jb.ldc + n) = v1;
        }
    }
}

// ---------------- persistent graph megakernel ----------------
// phases: [deg init, deg acc (layer0 only)], self, edge, relu, cos, partial-max,
//         exp+partial-sum, cross-agg; grid barriers between phases.
__global__ void __launch_bounds__(256)
graph_mega_kernel(int do_deg,
                  const int* __restrict__ qsrc, const int* __restrict__ qdst, int EQ,
                  const int* __restrict__ dsrc, const int* __restrict__ ddst, int ED,
                  const int* __restrict__ qi, const int* __restrict__ di, int EM,
                  const float* __restrict__ qh, const float* __restrict__ dh,
                  const float* __restrict__ qb, const float* __restrict__ db,
                  float* __restrict__ qdeg, float* __restrict__ ddeg,
                  float* __restrict__ qout, float* __restrict__ dout,
                  float* __restrict__ cosw)
{
    __shared__ float red[256];
    const int t = threadIdx.x;
    const int g = blockIdx.x * 256 + t;
    const int stride = gridDim.x * 256;
    const float4 z4 = {0.f, 0.f, 0.f, 0.f};

    if (do_deg) {
        for (int i = g; i < NQ + ND; i += stride) {
            if (i < NQ) qdeg[i] = 1.0f; else ddeg[i - NQ] = 1.0f;
        }
        grid_sync();
        for (int e = g; e < EQ + ED; e += stride) {
            if (e < EQ) atomicAdd(&qdeg[qdst[e]], 1.0f);
            else atomicAdd(&ddeg[ddst[e - EQ]], 1.0f);
        }
        grid_sync();
    }

    // ---- self ----
    for (int v = g; v < (NQ + ND) * 64; v += stride) {
        if (v < NQ * 64) {
            int i = v >> 6, c = v & 63;
            float4 h = ((const float4*)qh)[i * 64 + c];
            float inv = 1.0f / qdeg[i];
            float4 b = ((const float4*)qb)[c];
            float4 o = { h.x * inv + b.x, h.y * inv + b.y, h.z * inv + b.z, h.w * inv + b.w };
            ((float4*)qout)[i * 128 + c] = o;
            ((float4*)qout)[i * 128 + 64 + c] = z4;
        } else {
            int w = v - NQ * 64;
            int i = w >> 6, c = w & 63;
            float4 h = ((const float4*)dh)[i * 64 + c];
            float inv = 1.0f / ddeg[i];
            float4 b = ((const float4*)db)[c];
            float4 o = { h.x * inv + b.x, h.y * inv + b.y, h.z * inv + b.z, h.w * inv + b.w };
            ((float4*)dout)[i * 128 + c] = o;
            ((float4*)dout)[i * 128 + 64 + c] = z4;
        }
    }
    grid_sync();

    // ---- edge scatter ----
    for (int v = g; v < (EQ + ED) * 64; v += stride) {
        if (v < EQ * 64) {
            int e = v >> 6, c = v & 63;
            int s = qsrc[e], d = qdst[e];
            float coef = rsqrtf(qdeg[s]) * rsqrtf(qdeg[d]);
            float4 h = ((const float4*)qh)[s * 64 + c];
            float* o = qout + d * CAT + c * 4;
            atomicAdd(o + 0, coef * h.x);
            atomicAdd(o + 1, coef * h.y);
            atomicAdd(o + 2, coef * h.z);
            atomicAdd(o + 3, coef * h.w);
        } else {
            int w = v - EQ * 64;
            int e = w >> 6, c = w & 63;
            int s = dsrc[e], d = ddst[e];
            float coef = rsqrtf(ddeg[s]) * rsqrtf(ddeg[d]);
            float4 h = ((const float4*)dh)[s * 64 + c];
            float* o = dout + d * CAT + c * 4;
            atomicAdd(o + 0, coef * h.x);
            atomicAdd(o + 1, coef * h.y);
            atomicAdd(o + 2, coef * h.z);
            atomicAdd(o + 3, coef * h.w);
        }
    }
    grid_sync();

    // ---- relu (left half only) ----
    for (int v = g; v < (NQ + ND) * 64; v += stride) {
        float4* p;
        if (v < NQ * 64) p = (float4*)qout + (v >> 6) * 128 + (v & 63);
        else { int w = v - NQ * 64; p = (float4*)dout + (w >> 6) * 128 + (w & 63); }
        float4 x = *p;
        x.x = fmaxf(x.x, 0.f); x.y = fmaxf(x.y, 0.f);
        x.z = fmaxf(x.z, 0.f); x.w = fmaxf(x.w, 0.f);
        *p = x;
    }
    grid_sync();

    // ---- cosine (warp per edge, inline norms) ----
    {
        int gw = blockIdx.x * 8 + (t >> 5);
        int lane = t & 31;
        int wstride = gridDim.x * 8;
        for (int e = gw; e < EM; e += wstride) {
            const float* qp = qout + qi[e] * CAT;
            const float* dp = dout + di[e] * CAT;
            float qq = 0.f, dd = 0.f, qd = 0.f;
            for (int k = lane; k < DD; k += 32) {
                float a = qp[k], b = dp[k];
                qq += a * a; dd += b * b; qd += a * b;
            }
            #pragma unroll
            for (int o = 16; o; o >>= 1) {
                qq += __shfl_xor_sync(0xFFFFFFFFu, qq, o);
                dd += __shfl_xor_sync(0xFFFFFFFFu, dd, o);
                qd += __shfl_xor_sync(0xFFFFFFFFu, qd, o);
            }
            if (lane == 0)
                cosw[e] = qd / (fmaxf(sqrtf(qq), 1e-8f) * fmaxf(sqrtf(dd), 1e-8f));
        }
    }
    grid_sync();

    // ---- softmax partial max ----
    {
        float m = -1e30f;
        for (int e = g; e < EM; e += stride) m = fmaxf(m, cosw[e]);
        red[t] = m; __syncthreads();
        for (int s = 128; s; s >>= 1) {
            if (t < s) red[t] = fmaxf(red[t], red[t + s]);
            __syncthreads();
        }
        if (t == 0) g_pmax[blockIdx.x] = red[0];
    }
    grid_sync();

    // ---- exp + partial sum ----
    {
        float mx = -1e30f;
        for (int i = 0; i < (int)gridDim.x; i++) mx = fmaxf(mx, g_pmax[i]);
        float sum = 0.f;
        for (int e = g; e < EM; e += stride) {
            float x = expf(cosw[e] - mx);
            cosw[e] = x;
            sum += x;
        }
        red[t] = sum; __syncthreads();
        for (int s = 128; s; s >>= 1) {
            if (t < s) red[t] += red[t + s];
            __syncthreads();
        }
        if (t == 0) g_psum[blockIdx.x] = red[0];
    }
    grid_sync();

    // ---- cross aggregation (softmax scale folded in) ----
    {
        float tot = 0.f;
        for (int i = 0; i < (int)gridDim.x; i++) tot += g_psum[i];
        float inv = 1.0f / tot;
        for (int v = g; v < EM * 64; v += stride) {
            int e = v >> 6, c = v & 63;
            float we = cosw[e] * inv;
            int q = qi[e], d = di[e];
            float4 dv = ((const float4*)dout)[d * 128 + c];
            float4 qv = ((const float4*)qout)[q * 128 + c];
            float* qa = qout + q * CAT + DD + c * 4;
            float* da = dout + d * CAT + DD + c * 4;
            atomicAdd(qa + 0, we * dv.x);
            atomicAdd(qa + 1, we * dv.y);
            atomicAdd(qa + 2, we * dv.z);
            atomicAdd(qa + 3, we * dv.w);
            atomicAdd(da + 0, we * qv.x);
            atomicAdd(da + 1, we * qv.y);
            atomicAdd(da + 2, we * qv.z);
            atomicAdd(da + 3, we * qv.w);
        }
    }
}

// ---------------- HMMA pair-MLP kernel (unchanged) ----------------
#define SM_BQ   0
#define SM_B3   1024
#define SM_W4   1536
#define SM_RED  2048
#define SM_BD   4096
#define BD_STR  1032
#define SM_W3H  (SM_BD + 64 * BD_STR)
#define W3_STR  528
#define SM_W3L  (SM_W3H + 128 * W3_STR)
#define SM_PAIR_TOTAL (SM_W3L + 128 * W3_STR)

__global__ void __launch_bounds__(512, 1)
pair_hmma_kernel(const float* __restrict__ Bq, const float* __restrict__ Bd,
                 const __nv_bfloat16* __restrict__ w3hi, const __nv_bfloat16* __restrict__ w3lo,
                 const float* __restrict__ b3, const float* __restrict__ w4,
                 const float* __restrict__ b4, float* __restrict__ pred)
{
    extern __shared__ char smem[];
    const int t = threadIdx.x, lane = t & 31, wid = t >> 5;
    const int warp_m = wid & 3, warp_n = wid >> 2;
    const int j0 = blockIdx.x * 64;
    const int i0 = blockIdx.y * 8;

    for (int v = t; v < 64 * 128; v += 512) {
        int row = v >> 7, c = v & 127;
        *(float2*)(smem + SM_BD + row * BD_STR + c * 8) =
            ((const float2*)(Bd + (size_t)(j0 + row) * DD))[c];
    }
    for (int v = t; v < 128 * 32; v += 512) {
        int row = v >> 5, c = v & 31;
        *(uint4*)(smem + SM_W3H + row * W3_STR + c * 16) =
            ((const uint4*)(w3hi + (size_t)row * DD))[c];
        *(uint4*)(smem + SM_W3L + row * W3_STR + c * 16) =
            ((const uint4*)(w3lo + (size_t)row * DD))[c];
    }
    if (t < 32) ((uint4*)(smem + SM_B3))[t] = ((const uint4*)b3)[t];
    else if (t < 64) ((uint4*)(smem + SM_W4))[t - 32] = ((const uint4*)w4)[t - 32];
    const float b4v = b4[0];

    const float* b3s = (const float*)(smem + SM_B3);
    const float* w4s = (const float*)(smem + SM_W4);
    float* red = (float*)(smem + SM_RED);

    const int r_lo = warp_m * 16 + (lane >> 2);
    const char* bd_lo = smem + SM_BD + r_lo * BD_STR;
    const char* bd_hi = bd_lo + 8 * BD_STR;
    const int kq = (lane & 3) * 2;
    const int nrow = warp_n * 32 + (lane >> 2);

    for (int il = 0; il < 8; il++) {
        __syncthreads();
        if (t < 64) ((uint4*)(smem + SM_BQ))[t] = ((const uint4*)(Bq + (size_t)(i0 + il) * DD))[t];
        __syncthreads();

        float c[4][4];
        #pragma unroll
        for (int nt = 0; nt < 4; nt++)
            #pragma unroll
            for (int u = 0; u < 4; u++) c[nt][u] = 0.0f;

        #pragma unroll
        for (int ks = 0; ks < 16; ks++) {
            const int kb = ks * 16 + kq;
            float2 q0 = *(const float2*)(smem + SM_BQ + kb * 4);
            float2 q1 = *(const float2*)(smem + SM_BQ + (kb + 8) * 4);
            uint32_t ah[4], al[4];
            {
                float2 d = *(const float2*)(bd_lo + kb * 4);
                split_pack(fmaxf(d.x + q0.x, 0.0f), fmaxf(d.y + q0.y, 0.0f), ah[0], al[0]);
            }
            {
                float2 d = *(const float2*)(bd_hi + kb * 4);
                split_pack(fmaxf(d.x + q0.x, 0.0f), fmaxf(d.y + q0.y, 0.0f), ah[1], al[1]);
            }
            {
                float2 d = *(const float2*)(bd_lo + (kb + 8) * 4);
                split_pack(fmaxf(d.x + q1.x, 0.0f), fmaxf(d.y + q1.y, 0.0f), ah[2], al[2]);
            }
            {
                float2 d = *(const float2*)(bd_hi + (kb + 8) * 4);
                split_pack(fmaxf(d.x + q1.x, 0.0f), fmaxf(d.y + q1.y, 0.0f), ah[3], al[3]);
            }
            #pragma unroll
            for (int nt = 0; nt < 4; nt++) {
                const int roff = (nrow + nt * 8) * W3_STR + kb * 2;
                uint32_t bh0 = *(const uint32_t*)(smem + SM_W3H + roff);
                uint32_t bh1 = *(const uint32_t*)(smem + SM_W3H + roff + 16);
                uint32_t bl0 = *(const uint32_t*)(smem + SM_W3L + roff);
                uint32_t bl1 = *(const uint32_t*)(smem + SM_W3L + roff + 16);
                mma_bf16(c[nt], ah[0], ah[1], ah[2], ah[3], bh0, bh1);
                mma_bf16(c[nt], al[0], al[1], al[2], al[3], bh0, bh1);
                mma_bf16(c[nt], ah[0], ah[1], ah[2], ah[3], bl0, bl1);
            }
        }

        float s_lo = 0.0f, s_hi = 0.0f;
        #pragma unroll
        for (int nt = 0; nt < 4; nt++) {
            int n0 = warp_n * 32 + nt * 8 + (lane & 3) * 2;
            float b30 = b3s[n0], b31 = b3s[n0 + 1];
            float w40 = w4s[n0], w41 = w4s[n0 + 1];
            s_lo += fmaxf(c[nt][0] + b30, 0.0f) * w40 + fmaxf(c[nt][1] + b31, 0.0f) * w41;
            s_hi += fmaxf(c[nt][2] + b30, 0.0f) * w40 + fmaxf(c[nt][3] + b31, 0.0f) * w41;
        }
        s_lo += __shfl_xor_sync(0xFFFFFFFFu, s_lo, 1);
        s_lo += __shfl_xor_sync(0xFFFFFFFFu, s_lo, 2);
        s_hi += __shfl_xor_sync(0xFFFFFFFFu, s_hi, 1);
        s_hi += __shfl_xor_sync(0xFFFFFFFFu, s_hi, 2);
        if ((lane & 3) == 0) {
            red[r_lo * 4 + warp_n] = s_lo;
            red[(r_lo + 8) * 4 + warp_n] = s_hi;
        }
        __syncthreads();
        if (t < 64) {
            float v = red[t * 4] + red[t * 4 + 1] + red[t * 4 + 2] + red[t * 4 + 3] + b4v;
            v = v > 0.0f ? v : 0.0f;
            pred[(size_t)(i0 + il) * ND + j0 + t] = v;
        }
    }
}

// ---------------- host orchestration ----------------
extern "C" void kernel_launch(void* const* d_in, const int* in_sizes, int n_in,
                              void* d_out, int out_size)
{
    const float* qfeat = (const float*)d_in[0];
    const float* dfeat = (const float*)d_in[1];
    const int*   qe    = (const int*)d_in[2];
    const int*   de    = (const int*)d_in[3];
    const int*   qi    = (const int*)d_in[4];
    const int*   di    = (const int*)d_in[5];
    const float* q_w0 = (const float*)d_in[6];
    const float* q_b0 = (const float*)d_in[7];
    const float* q_w1 = (const float*)d_in[8];
    const float* q_b1 = (const float*)d_in[9];
    const float* d_w0 = (const float*)d_in[10];
    const float* d_b0 = (const float*)d_in[11];
    const float* d_w1 = (const float*)d_in[12];
    const float* d_b1 = (const float*)d_in[13];
    const float* w1 = (const float*)d_in[14];
    const float* b1 = (const float*)d_in[15];
    const float* w2 = (const float*)d_in[16];
    const float* b2 = (const float*)d_in[17];
    const float* w3 = (const float*)d_in[18];
    const float* b3 = (const float*)d_in[19];
    const float* w4 = (const float*)d_in[20];
    const float* b4 = (const float*)d_in[21];

    const int EQ = in_sizes[2] / 2;
    const int ED = in_sizes[3] / 2;
    const int EM = in_sizes[4];

    float *qh, *dh, *qB, *dB, *qdeg, *ddeg, *cosw, *Bqp, *Bdp;
    __nv_bfloat16 *wh, *wl;
    cudaGetSymbolAddress((void**)&qh, g_qh);
    cudaGetSymbolAddress((void**)&dh, g_dh);
    cudaGetSymbolAddress((void**)&qB, g_qB);
    cudaGetSymbolAddress((void**)&dB, g_dB);
    cudaGetSymbolAddress((void**)&qdeg, g_qdeg);
    cudaGetSymbolAddress((void**)&ddeg, g_ddeg);
    cudaGetSymbolAddress((void**)&cosw, g_cosw);
    cudaGetSymbolAddress((void**)&Bqp, g_Bq);
    cudaGetSymbolAddress((void**)&Bdp, g_Bd);
    cudaGetSymbolAddress((void**)&wh, g_wh);
    cudaGetSymbolAddress((void**)&wl, g_wl);

    float* out = (float*)d_out;
    float* qOut = out + NQ * ND;
    float* dOut = qOut + NQ * CAT;

    cudaFuncSetAttribute(hgemm_kernel, cudaFuncAttributeMaxDynamicSharedMemorySize, HG_SMEM);
    cudaFuncSetAttribute(pair_hmma_kernel, cudaFuncAttributeMaxDynamicSharedMemorySize,
                         SM_PAIR_TOTAL);

    // ---- 1. pack all weights ----
    PackArgs pa;
    pa.j[0] = { q_w0,               DD,  DD,  DD,  OFF_QW0 };
    pa.j[1] = { d_w0,               DD,  DD,  DD,  OFF_DW0 };
    pa.j[2] = { q_w1,               CAT, DD,  DD,  OFF_QW1 };
    pa.j[3] = { d_w1,               CAT, DD,  DD,  OFF_DW1 };
    pa.j[4] = { w1,                 CAT, CAT, CAT, OFF_W1T };
    pa.j[5] = { w1 + CAT * CAT,     CAT, CAT, CAT, OFF_W1B };
    pa.j[6] = { w2,                 CAT, DD,  DD,  OFF_W2  };
    pa.j[7] = { w3,                 DD,  128, 128, OFF_W3  };
    pack_kernel<<<dim3(256, 8), 256>>>(pa, wh, wl);

    // ---- 2. layer 0 ----
    {
        GemmJob jq = { qfeat, wh + OFF_QW0, wl + OFF_QW0, qh, nullptr, NQ, DD, DD, DD, DD };
        GemmJob jd = { dfeat, wh + OFF_DW0, wl + OFF_DW0, dh, nullptr, ND, DD, DD, DD, DD };
        hgemm_kernel<<<dim3(DD / 64, ND / 128, 2), 256, HG_SMEM>>>(jq, jd);
    }
    graph_mega_kernel<<<MEGA_CTAS, 256>>>(1, qe, qe + EQ, EQ, de, de + ED, ED,
                                          qi, di, EM, qh, dh, q_b0, d_b0,
                                          qdeg, ddeg, qB, dB, cosw);

    // ---- 3. layer 1 (outputs straight into d_out) ----
    {
        GemmJob jq = { qB, wh + OFF_QW1, wl + OFF_QW1, qh, nullptr, NQ, DD, CAT, CAT, DD };
        GemmJob jd = { dB, wh + OFF_DW1, wl + OFF_DW1, dh, nullptr, ND, DD, CAT, CAT, DD };
        hgemm_kernel<<<dim3(DD / 64, ND / 128, 2), 256, HG_SMEM>>>(jq, jd);
    }
    graph_mega_kernel<<<MEGA_CTAS, 256>>>(0, qe, qe + EQ, EQ, de, de + ED, ED,
                                          qi, di, EM, qh, dh, q_b1, d_b1,
                                          qdeg, ddeg, qOut, dOut, cosw);

    // ---- 4. final scoring (w1/w2 folded) ----
    {
        GemmJob jq = { qOut, wh + OFF_W1T, wl + OFF_W1T, qB, b1, NQ, CAT, CAT, CAT, CAT };
        GemmJob jd = { dOut, wh + OFF_W1B, wl + OFF_W1B, dB, nullptr, ND, CAT, CAT, CAT, CAT };
        hgemm_kernel<<<dim3(CAT / 64, ND / 128, 2), 256, HG_SMEM>>>(jq, jd);
    }
    {
        GemmJob jq = { qB, wh + OFF_W2, wl + OFF_W2, Bqp, b2, NQ, DD, CAT, CAT, DD };
        GemmJob jd = { dB, wh + OFF_W2, wl + OFF_W2, Bdp, nullptr, ND, DD, CAT, CAT, DD };
        hgemm_kernel<<<dim3(DD / 64, ND / 128, 2), 256, HG_SMEM>>>(jq, jd);
    }

    // ---- 5. pair MLP -> pred ----
    dim3 pg(ND / 64, NQ / 8);
    pair_hmma_kernel<<<pg, 512, SM_PAIR_TOTAL>>>(Bqp, Bdp, wh + OFF_W3, wl + OFF_W3,
                                                 b3, w4, b4, out);
}

// round 6
// speedup vs baseline: 1.2041x; 1.2041x over previous
#include <cuda_runtime.h>
#include <cuda_bf16.h>
#include <cstdint>
#include <math.h>

#define NQ 128
#define ND 1024
#define DD 256
#define CAT 512

// ---------------- device scratch ----------------
__device__ float g_qh[NQ * DD];
__device__ float g_dh[ND * DD];
__device__ float g_qB[NQ * CAT];
__device__ float g_dB[ND * CAT];
__device__ float g_qdeg[NQ];
__device__ float g_ddeg[ND];
__device__ float g_cosw[8192];
__device__ float g_Bq[NQ * DD];
__device__ float g_Bd[ND * DD];

// packed weights: [N][K] bf16, hi and lo parts
#define OFF_QW0 0
#define OFF_DW0 65536
#define OFF_QW1 131072
#define OFF_DW1 262144
#define OFF_W1T 393216
#define OFF_W1B 655360
#define OFF_W2  917504
#define OFF_W3  1048576
#define WPACK_TOTAL 1081344
__device__ __align__(16) __nv_bfloat16 g_wh[WPACK_TOTAL];
__device__ __align__(16) __nv_bfloat16 g_wl[WPACK_TOTAL];

// ---------------- shared helpers ----------------
__device__ __forceinline__ void mma_bf16(float c[4],
                                         uint32_t a0, uint32_t a1, uint32_t a2, uint32_t a3,
                                         uint32_t b0, uint32_t b1)
{
    asm volatile("mma.sync.aligned.m16n8k16.row.col.f32.bf16.bf16.f32 "
                 "{%0,%1,%2,%3}, {%4,%5,%6,%7}, {%8,%9}, {%0,%1,%2,%3};"
                 : "+f"(c[0]), "+f"(c[1]), "+f"(c[2]), "+f"(c[3])
                 : "r"(a0), "r"(a1), "r"(a2), "r"(a3), "r"(b0), "r"(b1));
}

__device__ __forceinline__ void split_pack(float v0, float v1, uint32_t& hi, uint32_t& lo)
{
    asm("cvt.rn.bf16x2.f32 %0, %1, %2;" : "=r"(hi) : "f"(v1), "f"(v0));
    float h0 = __uint_as_float(hi << 16);
    float h1 = __uint_as_float(hi & 0xffff0000u);
    float r0 = v0 - h0, r1 = v1 - h1;
    asm("cvt.rn.bf16x2.f32 %0, %1, %2;" : "=r"(lo) : "f"(r1), "f"(r0));
}

// ---------------- weight pack: transpose + bf16 split ----------------
struct PackJob { const float* src; int K, N, ld; int64_t off; };
struct PackArgs { PackJob j[8]; };

__global__ void pack_kernel(PackArgs pa, __nv_bfloat16* __restrict__ wh,
                            __nv_bfloat16* __restrict__ wl)
{
    __shared__ float tile[32][33];
    const PackJob jb = pa.j[blockIdx.y];
    int ntilesK = jb.K >> 5;
    int ntiles = ntilesK * (jb.N >> 5);
    if ((int)blockIdx.x >= ntiles) return;
    int kt = blockIdx.x % ntilesK, nt = blockIdx.x / ntilesK;
    int tx = threadIdx.x & 31, ty = threadIdx.x >> 5;
    #pragma unroll
    for (int p = 0; p < 4; p++) {
        int row = ty + p * 8;
        tile[row][tx] = jb.src[(size_t)(kt * 32 + row) * jb.ld + nt * 32 + tx];
    }
    __syncthreads();
    #pragma unroll
    for (int p = 0; p < 4; p++) {
        int row = ty + p * 8;
        float v = tile[tx][row];
        __nv_bfloat16 h = __float2bfloat16(v);
        float r = v - __bfloat162float(h);
        size_t o = jb.off + (size_t)(nt * 32 + row) * jb.K + kt * 32 + tx;
        wh[o] = h;
        wl[o] = __float2bfloat16(r);
    }
}

// ---------------- HMMA split-bf16 GEMM, 64x64 tiles ----------------
// C[M,N] = A[M,K](f32) @ B, B pre-split transposed BT[n][k] bf16 hi/lo.
// CTA tile 64x64, 8 warps (2 m x 4 n), K-chunk 64, 2 CTAs/SM overlap.
struct GemmJob {
    const float* A;
    const __nv_bfloat16* Bh;
    const __nv_bfloat16* Bl;
    float* C;
    const float* bias;
    int M, N, K, lda, ldc;
};

#define HG_A    0
#define HG_ASTR 288
#define HG_BH   18432
#define HG_BL   27648
#define HG_BSTR 144
#define HG_SMEM 36864

__global__ void __launch_bounds__(256, 2)
hgemm_kernel(GemmJob j0, GemmJob j1)
{
    GemmJob jb = (blockIdx.z == 0) ? j0 : j1;
    const int n0 = blockIdx.x * 64;
    const int m0 = blockIdx.y * 64;
    if (n0 >= jb.N || m0 >= jb.M) return;
    extern __shared__ char sm[];
    const int t = threadIdx.x, lane = t & 31, wid = t >> 5;
    const int warp_m = wid & 1, warp_n = wid >> 1;
    const int qr = lane >> 2, qk = (lane & 3) * 2;
    float acc[2][2][4] = {};

    for (int kc = 0; kc < jb.K; kc += 64) {
        __syncthreads();
        {   // A fill: 64 rows x 64 f32 (4 threads/row, 4 float4 each)
            int row = t >> 2, c4 = (t & 3) * 4;
            const float4* src = (const float4*)(jb.A + (size_t)(m0 + row) * jb.lda + kc) + c4;
            float4* dst = (float4*)(sm + HG_A + row * HG_ASTR + c4 * 16);
            #pragma unroll
            for (int i = 0; i < 4; i++) dst[i] = src[i];
        }
        #pragma unroll
        for (int p = 0; p < 2; p++) {   // B fill: 64 n-rows x 64 k bf16 (hi+lo)
            int idx = t + p * 256;
            int row = idx >> 3, c = idx & 7;
            size_t go = (size_t)(n0 + row) * jb.K + kc + c * 8;
            *(uint4*)(sm + HG_BH + row * HG_BSTR + c * 16) = *(const uint4*)(jb.Bh + go);
            *(uint4*)(sm + HG_BL + row * HG_BSTR + c * 16) = *(const uint4*)(jb.Bl + go);
        }
        __syncthreads();
        #pragma unroll
        for (int kk = 0; kk < 64; kk += 16) {
            uint32_t bh[2][2], bl[2][2];
            #pragma unroll
            for (int f = 0; f < 2; f++) {
                int n = warp_n * 16 + f * 8 + qr;
                const char* bp = sm + n * HG_BSTR + (kk + qk) * 2;
                bh[f][0] = *(const uint32_t*)(bp + HG_BH);
                bh[f][1] = *(const uint32_t*)(bp + HG_BH + 16);
                bl[f][0] = *(const uint32_t*)(bp + HG_BL);
                bl[f][1] = *(const uint32_t*)(bp + HG_BL + 16);
            }
            #pragma unroll
            for (int s = 0; s < 2; s++) {
                int r = warp_m * 32 + s * 16 + qr;
                const char* ap = sm + HG_A + r * HG_ASTR + (kk + qk) * 4;
                float2 a0 = *(const float2*)ap;
                float2 a1 = *(const float2*)(ap + 8 * HG_ASTR);
                float2 a2 = *(const float2*)(ap + 32);
                float2 a3 = *(const float2*)(ap + 8 * HG_ASTR + 32);
                uint32_t ah[4], al[4];
                split_pack(a0.x, a0.y, ah[0], al[0]);
                split_pack(a1.x, a1.y, ah[1], al[1]);
                split_pack(a2.x, a2.y, ah[2], al[2]);
                split_pack(a3.x, a3.y, ah[3], al[3]);
                #pragma unroll
                for (int f = 0; f < 2; f++) {
                    mma_bf16(acc[s][f], ah[0], ah[1], ah[2], ah[3], bh[f][0], bh[f][1]);
                    mma_bf16(acc[s][f], al[0], al[1], al[2], al[3], bh[f][0], bh[f][1]);
                    mma_bf16(acc[s][f], ah[0], ah[1], ah[2], ah[3], bl[f][0], bl[f][1]);
                }
            }
        }
    }
    #pragma unroll
    for (int s = 0; s < 2; s++) {
        int r = m0 + warp_m * 32 + s * 16 + qr;
        #pragma unroll
        for (int f = 0; f < 2; f++) {
            int n = n0 + warp_n * 16 + f * 8 + qk;
            float bs0 = jb.bias ? jb.bias[n] : 0.0f;
            float bs1 = jb.bias ? jb.bias[n + 1] : 0.0f;
            float2 v0 = { acc[s][f][0] + bs0, acc[s][f][1] + bs1 };
            float2 v1 = { acc[s][f][2] + bs0, acc[s][f][3] + bs1 };
            *(float2*)(jb.C + (size_t)r * jb.ldc + n) = v0;
            *(float2*)(jb.C + (size_t)(r + 8) * jb.ldc + n) = v1;
        }
    }
}

// ---------------- fused graph kernels (R4, unchanged) ----------------
__global__ void deg_init_kernel(float* qdeg, float* ddeg)
{
    int i = blockIdx.x * blockDim.x + threadIdx.x;
    if (i < NQ) qdeg[i] = 1.0f;
    else if (i < NQ + ND) ddeg[i - NQ] = 1.0f;
}

__global__ void deg_acc_kernel(const int* __restrict__ qdst, int EQ,
                               const int* __restrict__ ddst, int ED,
                               float* qdeg, float* ddeg)
{
    int e = blockIdx.x * blockDim.x + threadIdx.x;
    if (e < EQ) atomicAdd(&qdeg[qdst[e]], 1.0f);
    else if (e < EQ + ED) atomicAdd(&ddeg[ddst[e - EQ]], 1.0f);
}

__global__ void self_fused_kernel(const float* __restrict__ qh, const float* __restrict__ dh,
                                  const float* __restrict__ qdeg, const float* __restrict__ ddeg,
                                  const float* __restrict__ qb, const float* __restrict__ db,
                                  float* __restrict__ qout, float* __restrict__ dout)
{
    const float4 z = {0.f, 0.f, 0.f, 0.f};
    int v = blockIdx.x * blockDim.x + threadIdx.x;
    if (v < NQ * 64) {
        int i = v >> 6, c = v & 63;
        float4 h = ((const float4*)qh)[i * 64 + c];
        float inv = 1.0f / qdeg[i];
        float4 b = ((const float4*)qb)[c];
        float4 o = { h.x * inv + b.x, h.y * inv + b.y, h.z * inv + b.z, h.w * inv + b.w };
        ((float4*)qout)[i * 128 + c] = o;
        ((float4*)qout)[i * 128 + 64 + c] = z;
    } else if (v < (NQ + ND) * 64) {
        v -= NQ * 64;
        int i = v >> 6, c = v & 63;
        float4 h = ((const float4*)dh)[i * 64 + c];
        float inv = 1.0f / ddeg[i];
        float4 b = ((const float4*)db)[c];
        float4 o = { h.x * inv + b.x, h.y * inv + b.y, h.z * inv + b.z, h.w * inv + b.w };
        ((float4*)dout)[i * 128 + c] = o;
        ((float4*)dout)[i * 128 + 64 + c] = z;
    }
}

__global__ void edge_fused_kernel(const int* __restrict__ qsrc, const int* __restrict__ qdst, int EQ,
                                  const int* __restrict__ dsrc, const int* __restrict__ ddst, int ED,
                                  const float* __restrict__ qh, const float* __restrict__ dh,
                                  const float* __restrict__ qdeg, const float* __restrict__ ddeg,
                                  float* __restrict__ qout, float* __restrict__ dout)
{
    int v = blockIdx.x * blockDim.x + threadIdx.x;
    if (v < EQ * 64) {
        int e = v >> 6, c = v & 63;
        int s = qsrc[e], d = qdst[e];
        float coef = rsqrtf(qdeg[s]) * rsqrtf(qdeg[d]);
        float4 h = ((const float4*)qh)[s * 64 + c];
        float* o = qout + d * CAT + c * 4;
        atomicAdd(o + 0, coef * h.x);
        atomicAdd(o + 1, coef * h.y);
        atomicAdd(o + 2, coef * h.z);
        atomicAdd(o + 3, coef * h.w);
    } else if (v < (EQ + ED) * 64) {
        v -= EQ * 64;
        int e = v >> 6, c = v & 63;
        int s = dsrc[e], d = ddst[e];
        float coef = rsqrtf(ddeg[s]) * rsqrtf(ddeg[d]);
        float4 h = ((const float4*)dh)[s * 64 + c];
        float* o = dout + d * CAT + c * 4;
        atomicAdd(o + 0, coef * h.x);
        atomicAdd(o + 1, coef * h.y);
        atomicAdd(o + 2, coef * h.z);
        atomicAdd(o + 3, coef * h.w);
    }
}

__global__ void relu_fused_kernel(float* __restrict__ qout, float* __restrict__ dout)
{
    int v = blockIdx.x * blockDim.x + threadIdx.x;
    float4* p;
    if (v < NQ * 64) p = (float4*)qout + (v >> 6) * 128 + (v & 63);
    else if (v < (NQ + ND) * 64) { v -= NQ * 64; p = (float4*)dout + (v >> 6) * 128 + (v & 63); }
    else return;
    float4 x = *p;
    x.x = fmaxf(x.x, 0.f); x.y = fmaxf(x.y, 0.f);
    x.z = fmaxf(x.z, 0.f); x.w = fmaxf(x.w, 0.f);
    *p = x;
}

__global__ void cos_norm_kernel(const int* __restrict__ qi, const int* __restrict__ di, int E,
                                const float* __restrict__ qbuf, const float* __restrict__ dbuf,
                                float* __restrict__ cosw)
{
    int e = blockIdx.x * (blockDim.x >> 5) + (threadIdx.x >> 5);
    int lane = threadIdx.x & 31;
    if (e >= E) return;
    const float* qp = qbuf + qi[e] * CAT;
    const float* dp = dbuf + di[e] * CAT;
    float qq = 0.f, dd = 0.f, qd = 0.f;
    for (int k = lane; k < DD; k += 32) {
        float a = qp[k], b = dp[k];
        qq += a * a; dd += b * b; qd += a * b;
    }
    #pragma unroll
    for (int o = 16; o; o >>= 1) {
        qq += __shfl_xor_sync(0xFFFFFFFFu, qq, o);
        dd += __shfl_xor_sync(0xFFFFFFFFu, dd, o);
        qd += __shfl_xor_sync(0xFFFFFFFFu, qd, o);
    }
    if (lane == 0)
        cosw[e] = qd / (fmaxf(sqrtf(qq), 1e-8f) * fmaxf(sqrtf(dd), 1e-8f));
}

__global__ void softmax_kernel(float* __restrict__ cosw, int E)
{
    __shared__ float red[1024];
    int t = threadIdx.x;
    float m = -1e30f;
    for (int e = t; e < E; e += 1024) m = fmaxf(m, cosw[e]);
    red[t] = m; __syncthreads();
    for (int s = 512; s; s >>= 1) { if (t < s) red[t] = fmaxf(red[t], red[t + s]); __syncthreads(); }
    float mx = red[0]; __syncthreads();
    float sum = 0.f;
    for (int e = t; e < E; e += 1024) sum += expf(cosw[e] - mx);
    red[t] = sum; __syncthreads();
    for (int s = 512; s; s >>= 1) { if (t < s) red[t] += red[t + s]; __syncthreads(); }
    float inv = 1.0f / red[0];
    for (int e = t; e < E; e += 1024) cosw[e] = expf(cosw[e] - mx) * inv;
}

__global__ void cross_agg_kernel(const int* __restrict__ qi, const int* __restrict__ di, int E,
                                 float* __restrict__ qbuf, float* __restrict__ dbuf,
                                 const float* __restrict__ w)
{
    int v = blockIdx.x * blockDim.x + threadIdx.x;
    if (v >= E * 64) return;
    int e = v >> 6, c = v & 63;
    float we = w[e];
    int q = qi[e], d = di[e];
    float4 dv = ((const float4*)dbuf)[d * 128 + c];
    float4 qv = ((const float4*)qbuf)[q * 128 + c];
    float* qa = qbuf + q * CAT + DD + c * 4;
    float* da = dbuf + d * CAT + DD + c * 4;
    atomicAdd(qa + 0, we * dv.x);
    atomicAdd(qa + 1, we * dv.y);
    atomicAdd(qa + 2, we * dv.z);
    atomicAdd(qa + 3, we * dv.w);
    atomicAdd(da + 0, we * qv.x);
    atomicAdd(da + 1, we * qv.y);
    atomicAdd(da + 2, we * qv.z);
    atomicAdd(da + 3, we * qv.w);
}

// ---------------- HMMA pair-MLP kernel (unchanged) ----------------
#define SM_BQ   0
#define SM_B3   1024
#define SM_W4   1536
#define SM_RED  2048
#define SM_BD   4096
#define BD_STR  1032
#define SM_W3H  (SM_BD + 64 * BD_STR)
#define W3_STR  528
#define SM_W3L  (SM_W3H + 128 * W3_STR)
#define SM_PAIR_TOTAL (SM_W3L + 128 * W3_STR)

__global__ void __launch_bounds__(512, 1)
pair_hmma_kernel(const float* __restrict__ Bq, const float* __restrict__ Bd,
                 const __nv_bfloat16* __restrict__ w3hi, const __nv_bfloat16* __restrict__ w3lo,
                 const float* __restrict__ b3, const float* __restrict__ w4,
                 const float* __restrict__ b4, float* __restrict__ pred)
{
    extern __shared__ char smem[];
    const int t = threadIdx.x, lane = t & 31, wid = t >> 5;
    const int warp_m = wid & 3, warp_n = wid >> 2;
    const int j0 = blockIdx.x * 64;
    const int i0 = blockIdx.y * 8;

    for (int v = t; v < 64 * 128; v += 512) {
        int row = v >> 7, c = v & 127;
        *(float2*)(smem + SM_BD + row * BD_STR + c * 8) =
            ((const float2*)(Bd + (size_t)(j0 + row) * DD))[c];
    }
    for (int v = t; v < 128 * 32; v += 512) {
        int row = v >> 5, c = v & 31;
        *(uint4*)(smem + SM_W3H + row * W3_STR + c * 16) =
            ((const uint4*)(w3hi + (size_t)row * DD))[c];
        *(uint4*)(smem + SM_W3L + row * W3_STR + c * 16) =
            ((const uint4*)(w3lo + (size_t)row * DD))[c];
    }
    if (t < 32) ((uint4*)(smem + SM_B3))[t] = ((const uint4*)b3)[t];
    else if (t < 64) ((uint4*)(smem + SM_W4))[t - 32] = ((const uint4*)w4)[t - 32];
    const float b4v = b4[0];

    const float* b3s = (const float*)(smem + SM_B3);
    const float* w4s = (const float*)(smem + SM_W4);
    float* red = (float*)(smem + SM_RED);

    const int r_lo = warp_m * 16 + (lane >> 2);
    const char* bd_lo = smem + SM_BD + r_lo * BD_STR;
    const char* bd_hi = bd_lo + 8 * BD_STR;
    const int kq = (lane & 3) * 2;
    const int nrow = warp_n * 32 + (lane >> 2);

    for (int il = 0; il < 8; il++) {
        __syncthreads();
        if (t < 64) ((uint4*)(smem + SM_BQ))[t] = ((const uint4*)(Bq + (size_t)(i0 + il) * DD))[t];
        __syncthreads();

        float c[4][4];
        #pragma unroll
        for (int nt = 0; nt < 4; nt++)
            #pragma unroll
            for (int u = 0; u < 4; u++) c[nt][u] = 0.0f;

        #pragma unroll
        for (int ks = 0; ks < 16; ks++) {
            const int kb = ks * 16 + kq;
            float2 q0 = *(const float2*)(smem + SM_BQ + kb * 4);
            float2 q1 = *(const float2*)(smem + SM_BQ + (kb + 8) * 4);
            uint32_t ah[4], al[4];
            {
                float2 d = *(const float2*)(bd_lo + kb * 4);
                split_pack(fmaxf(d.x + q0.x, 0.0f), fmaxf(d.y + q0.y, 0.0f), ah[0], al[0]);
            }
            {
                float2 d = *(const float2*)(bd_hi + kb * 4);
                split_pack(fmaxf(d.x + q0.x, 0.0f), fmaxf(d.y + q0.y, 0.0f), ah[1], al[1]);
            }
            {
                float2 d = *(const float2*)(bd_lo + (kb + 8) * 4);
                split_pack(fmaxf(d.x + q1.x, 0.0f), fmaxf(d.y + q1.y, 0.0f), ah[2], al[2]);
            }
            {
                float2 d = *(const float2*)(bd_hi + (kb + 8) * 4);
                split_pack(fmaxf(d.x + q1.x, 0.0f), fmaxf(d.y + q1.y, 0.0f), ah[3], al[3]);
            }
            #pragma unroll
            for (int nt = 0; nt < 4; nt++) {
                const int roff = (nrow + nt * 8) * W3_STR + kb * 2;
                uint32_t bh0 = *(const uint32_t*)(smem + SM_W3H + roff);
                uint32_t bh1 = *(const uint32_t*)(smem + SM_W3H + roff + 16);
                uint32_t bl0 = *(const uint32_t*)(smem + SM_W3L + roff);
                uint32_t bl1 = *(const uint32_t*)(smem + SM_W3L + roff + 16);
                mma_bf16(c[nt], ah[0], ah[1], ah[2], ah[3], bh0, bh1);
                mma_bf16(c[nt], al[0], al[1], al[2], al[3], bh0, bh1);
                mma_bf16(c[nt], ah[0], ah[1], ah[2], ah[3], bl0, bl1);
            }
        }

        float s_lo = 0.0f, s_hi = 0.0f;
        #pragma unroll
        for (int nt = 0; nt < 4; nt++) {
            int n0 = warp_n * 32 + nt * 8 + (lane & 3) * 2;
            float b30 = b3s[n0], b31 = b3s[n0 + 1];
            float w40 = w4s[n0], w41 = w4s[n0 + 1];
            s_lo += fmaxf(c[nt][0] + b30, 0.0f) * w40 + fmaxf(c[nt][1] + b31, 0.0f) * w41;
            s_hi += fmaxf(c[nt][2] + b30, 0.0f) * w40 + fmaxf(c[nt][3] + b31, 0.0f) * w41;
        }
        s_lo += __shfl_xor_sync(0xFFFFFFFFu, s_lo, 1);
        s_lo += __shfl_xor_sync(0xFFFFFFFFu, s_lo, 2);
        s_hi += __shfl_xor_sync(0xFFFFFFFFu, s_hi, 1);
        s_hi += __shfl_xor_sync(0xFFFFFFFFu, s_hi, 2);
        if ((lane & 3) == 0) {
            red[r_lo * 4 + warp_n] = s_lo;
            red[(r_lo + 8) * 4 + warp_n] = s_hi;
        }
        __syncthreads();
        if (t < 64) {
            float v = red[t * 4] + red[t * 4 + 1] + red[t * 4 + 2] + red[t * 4 + 3] + b4v;
            v = v > 0.0f ? v : 0.0f;
            pred[(size_t)(i0 + il) * ND + j0 + t] = v;
        }
    }
}

// ---------------- host orchestration ----------------
extern "C" void kernel_launch(void* const* d_in, const int* in_sizes, int n_in,
                              void* d_out, int out_size)
{
    const float* qfeat = (const float*)d_in[0];
    const float* dfeat = (const float*)d_in[1];
    const int*   qe    = (const int*)d_in[2];
    const int*   de    = (const int*)d_in[3];
    const int*   qi    = (const int*)d_in[4];
    const int*   di    = (const int*)d_in[5];
    const float* q_w0 = (const float*)d_in[6];
    const float* q_b0 = (const float*)d_in[7];
    const float* q_w1 = (const float*)d_in[8];
    const float* q_b1 = (const float*)d_in[9];
    const float* d_w0 = (const float*)d_in[10];
    const float* d_b0 = (const float*)d_in[11];
    const float* d_w1 = (const float*)d_in[12];
    const float* d_b1 = (const float*)d_in[13];
    const float* w1 = (const float*)d_in[14];
    const float* b1 = (const float*)d_in[15];
    const float* w2 = (const float*)d_in[16];
    const float* b2 = (const float*)d_in[17];
    const float* w3 = (const float*)d_in[18];
    const float* b3 = (const float*)d_in[19];
    const float* w4 = (const float*)d_in[20];
    const float* b4 = (const float*)d_in[21];

    const int EQ = in_sizes[2] / 2;
    const int ED = in_sizes[3] / 2;
    const int EM = in_sizes[4];

    float *qh, *dh, *qB, *dB, *qdeg, *ddeg, *cosw, *Bqp, *Bdp;
    __nv_bfloat16 *wh, *wl;
    cudaGetSymbolAddress((void**)&qh, g_qh);
    cudaGetSymbolAddress((void**)&dh, g_dh);
    cudaGetSymbolAddress((void**)&qB, g_qB);
    cudaGetSymbolAddress((void**)&dB, g_dB);
    cudaGetSymbolAddress((void**)&qdeg, g_qdeg);
    cudaGetSymbolAddress((void**)&ddeg, g_ddeg);
    cudaGetSymbolAddress((void**)&cosw, g_cosw);
    cudaGetSymbolAddress((void**)&Bqp, g_Bq);
    cudaGetSymbolAddress((void**)&Bdp, g_Bd);
    cudaGetSymbolAddress((void**)&wh, g_wh);
    cudaGetSymbolAddress((void**)&wl, g_wl);

    float* out = (float*)d_out;
    float* qOut = out + NQ * ND;
    float* dOut = qOut + NQ * CAT;

    cudaFuncSetAttribute(hgemm_kernel, cudaFuncAttributeMaxDynamicSharedMemorySize, HG_SMEM);
    cudaFuncSetAttribute(pair_hmma_kernel, cudaFuncAttributeMaxDynamicSharedMemorySize,
                         SM_PAIR_TOTAL);

    // ---- 1. pack all weights ----
    PackArgs pa;
    pa.j[0] = { q_w0,               DD,  DD,  DD,  OFF_QW0 };
    pa.j[1] = { d_w0,               DD,  DD,  DD,  OFF_DW0 };
    pa.j[2] = { q_w1,               CAT, DD,  DD,  OFF_QW1 };
    pa.j[3] = { d_w1,               CAT, DD,  DD,  OFF_DW1 };
    pa.j[4] = { w1,                 CAT, CAT, CAT, OFF_W1T };
    pa.j[5] = { w1 + CAT * CAT,     CAT, CAT, CAT, OFF_W1B };
    pa.j[6] = { w2,                 CAT, DD,  DD,  OFF_W2  };
    pa.j[7] = { w3,                 DD,  128, 128, OFF_W3  };
    pack_kernel<<<dim3(256, 8), 256>>>(pa, wh, wl);

    // ---- 2. degrees (once) ----
    deg_init_kernel<<<5, 256>>>(qdeg, ddeg);
    deg_acc_kernel<<<(EQ + ED + 255) / 256, 256>>>(qe + EQ, EQ, de + ED, ED, qdeg, ddeg);

    const int selfBlocks = (NQ + ND) * 64 / 256;
    const int edgeBlocks = (EQ + ED) * 64 / 256;

    // ---- 3. layer 0 ----
    {
        GemmJob jq = { qfeat, wh + OFF_QW0, wl + OFF_QW0, qh, nullptr, NQ, DD, DD, DD, DD };
        GemmJob jd = { dfeat, wh + OFF_DW0, wl + OFF_DW0, dh, nullptr, ND, DD, DD, DD, DD };
        hgemm_kernel<<<dim3(DD / 64, ND / 64, 2), 256, HG_SMEM>>>(jq, jd);
    }
    self_fused_kernel<<<selfBlocks, 256>>>(qh, dh, qdeg, ddeg, q_b0, d_b0, qB, dB);
    edge_fused_kernel<<<edgeBlocks, 256>>>(qe, qe + EQ, EQ, de, de + ED, ED,
                                           qh, dh, qdeg, ddeg, qB, dB);
    relu_fused_kernel<<<selfBlocks, 256>>>(qB, dB);
    cos_norm_kernel<<<(EM + 7) / 8, 256>>>(qi, di, EM, qB, dB, cosw);
    softmax_kernel<<<1, 1024>>>(cosw, EM);
    cross_agg_kernel<<<EM / 4, 256>>>(qi, di, EM, qB, dB, cosw);

    // ---- 4. layer 1 (outputs straight into d_out) ----
    {
        GemmJob jq = { qB, wh + OFF_QW1, wl + OFF_QW1, qh, nullptr, NQ, DD, CAT, CAT, DD };
        GemmJob jd = { dB, wh + OFF_DW1, wl + OFF_DW1, dh, nullptr, ND, DD, CAT, CAT, DD };
        hgemm_kernel<<<dim3(DD / 64, ND / 64, 2), 256, HG_SMEM>>>(jq, jd);
    }
    self_fused_kernel<<<selfBlocks, 256>>>(qh, dh, qdeg, ddeg, q_b1, d_b1, qOut, dOut);
    edge_fused_kernel<<<edgeBlocks, 256>>>(qe, qe + EQ, EQ, de, de + ED, ED,
                                           qh, dh, qdeg, ddeg, qOut, dOut);
    relu_fused_kernel<<<selfBlocks, 256>>>(qOut, dOut);
    cos_norm_kernel<<<(EM + 7) / 8, 256>>>(qi, di, EM, qOut, dOut, cosw);
    softmax_kernel<<<1, 1024>>>(cosw, EM);
    cross_agg_kernel<<<EM / 4, 256>>>(qi, di, EM, qOut, dOut, cosw);

    // ---- 5. final scoring (w1/w2 folded) ----
    {
        GemmJob jq = { qOut, wh + OFF_W1T, wl + OFF_W1T, qB, b1, NQ, CAT, CAT, CAT, CAT };
        GemmJob jd = { dOut, wh + OFF_W1B, wl + OFF_W1B, dB, nullptr, ND, CAT, CAT, CAT, CAT };
        hgemm_kernel<<<dim3(CAT / 64, ND / 64, 2), 256, HG_SMEM>>>(jq, jd);
    }
    {
        GemmJob jq = { qB, wh + OFF_W2, wl + OFF_W2, Bqp, b2, NQ, DD, CAT, CAT, DD };
        GemmJob jd = { dB, wh + OFF_W2, wl + OFF_W2, Bdp, nullptr, ND, DD, CAT, CAT, DD };
        hgemm_kernel<<<dim3(DD / 64, ND / 64, 2), 256, HG_SMEM>>>(jq, jd);
    }

    // ---- 6. pair MLP -> pred ----
    dim3 pg(ND / 64, NQ / 8);
    pair_hmma_kernel<<<pg, 512, SM_PAIR_TOTAL>>>(Bqp, Bdp, wh + OFF_W3, wl + OFF_W3,
                                                 b3, w4, b4, out);
}

// round 7
// speedup vs baseline: 1.3385x; 1.1116x over previous
#include <cuda_runtime.h>
#include <cuda_bf16.h>
#include <cstdint>
#include <math.h>

#define NQ 128
#define ND 1024
#define DD 256
#define CAT 512
#define EQMAX 2048
#define EDMAX 32768
#define EMMAX 8192

// ---------------- device scratch ----------------
__device__ float g_qh[NQ * DD];
__device__ float g_dh[ND * DD];
__device__ float g_qB[NQ * CAT];
__device__ float g_dB[ND * CAT];
__device__ float g_cosw[EMMAX];
__device__ float g_Bq[NQ * DD];
__device__ float g_Bd[ND * DD];

// CSR structures (static graphs -> built once)
__device__ int g_qcnt[NQ],  g_qoff[NQ + 1],  g_qsrcs[EQMAX];
__device__ int g_dcnt[ND],  g_doff[ND + 1],  g_dsrcs[EDMAX];
__device__ int g_mqcnt[NQ], g_mqoff[NQ + 1], g_mqe[EMMAX];
__device__ int g_mdcnt[ND], g_mdoff[ND + 1], g_mde[EMMAX];

// packed weights: [N][K] bf16, hi and lo parts
#define OFF_QW0 0
#define OFF_DW0 65536
#define OFF_QW1 131072
#define OFF_DW1 262144
#define OFF_W1T 393216
#define OFF_W1B 655360
#define OFF_W2  917504
#define OFF_W3  1048576
#define WPACK_TOTAL 1081344
__device__ __align__(16) __nv_bfloat16 g_wh[WPACK_TOTAL];
__device__ __align__(16) __nv_bfloat16 g_wl[WPACK_TOTAL];

// ---------------- shared helpers ----------------
__device__ __forceinline__ void mma_bf16(float c[4],
                                         uint32_t a0, uint32_t a1, uint32_t a2, uint32_t a3,
                                         uint32_t b0, uint32_t b1)
{
    asm volatile("mma.sync.aligned.m16n8k16.row.col.f32.bf16.bf16.f32 "
                 "{%0,%1,%2,%3}, {%4,%5,%6,%7}, {%8,%9}, {%0,%1,%2,%3};"
                 : "+f"(c[0]), "+f"(c[1]), "+f"(c[2]), "+f"(c[3])
                 : "r"(a0), "r"(a1), "r"(a2), "r"(a3), "r"(b0), "r"(b1));
}

__device__ __forceinline__ void split_pack(float v0, float v1, uint32_t& hi, uint32_t& lo)
{
    asm("cvt.rn.bf16x2.f32 %0, %1, %2;" : "=r"(hi) : "f"(v1), "f"(v0));
    float h0 = __uint_as_float(hi << 16);
    float h1 = __uint_as_float(hi & 0xffff0000u);
    float r0 = v0 - h0, r1 = v1 - h1;
    asm("cvt.rn.bf16x2.f32 %0, %1, %2;" : "=r"(lo) : "f"(r1), "f"(r0));
}

// ---------------- weight pack: transpose + bf16 split ----------------
struct PackJob { const float* src; int K, N, ld; int64_t off; };
struct PackArgs { PackJob j[8]; };

__global__ void pack_kernel(PackArgs pa, __nv_bfloat16* __restrict__ wh,
                            __nv_bfloat16* __restrict__ wl)
{
    __shared__ float tile[32][33];
    const PackJob jb = pa.j[blockIdx.y];
    int ntilesK = jb.K >> 5;
    int ntiles = ntilesK * (jb.N >> 5);
    if ((int)blockIdx.x >= ntiles) return;
    int kt = blockIdx.x % ntilesK, nt = blockIdx.x / ntilesK;
    int tx = threadIdx.x & 31, ty = threadIdx.x >> 5;
    #pragma unroll
    for (int p = 0; p < 4; p++) {
        int row = ty + p * 8;
        tile[row][tx] = jb.src[(size_t)(kt * 32 + row) * jb.ld + nt * 32 + tx];
    }
    __syncthreads();
    #pragma unroll
    for (int p = 0; p < 4; p++) {
        int row = ty + p * 8;
        float v = tile[tx][row];
        __nv_bfloat16 h = __float2bfloat16(v);
        float r = v - __bfloat162float(h);
        size_t o = jb.off + (size_t)(nt * 32 + row) * jb.K + kt * 32 + tx;
        wh[o] = h;
        wl[o] = __float2bfloat16(r);
    }
}

// ---------------- CSR build (once; graphs static across layers) ----------------
__global__ void csr_zero_kernel()
{
    int i = blockIdx.x * blockDim.x + threadIdx.x;
    if (i < NQ) { g_qcnt[i] = 0; g_mqcnt[i] = 0; }
    if (i < ND) { g_dcnt[i] = 0; g_mdcnt[i] = 0; }
}

__global__ void csr_count_kernel(const int* __restrict__ qdst, int EQ,
                                 const int* __restrict__ ddst, int ED,
                                 const int* __restrict__ qi, const int* __restrict__ di, int EM)
{
    int e = blockIdx.x * blockDim.x + threadIdx.x;
    if (e < EQ) atomicAdd(&g_qcnt[qdst[e]], 1);
    else if (e < EQ + ED) atomicAdd(&g_dcnt[ddst[e - EQ]], 1);
    else if (e < EQ + ED + EM) atomicAdd(&g_mqcnt[qi[e - EQ - ED]], 1);
    else if (e < EQ + ED + 2 * EM) atomicAdd(&g_mdcnt[di[e - EQ - ED - EM]], 1);
}

// 4 segments: blockIdx.x selects (cnt,off,n). Hillis-Steele inclusive scan,
// writes exclusive offsets, zeroes cnt (reused as fill cursor).
__global__ void __launch_bounds__(1024) csr_scan_kernel()
{
    __shared__ int s[1024];
    int* cnt; int* off; int n;
    switch (blockIdx.x) {
        case 0: cnt = g_qcnt;  off = g_qoff;  n = NQ; break;
        case 1: cnt = g_dcnt;  off = g_doff;  n = ND; break;
        case 2: cnt = g_mqcnt; off = g_mqoff; n = NQ; break;
        default: cnt = g_mdcnt; off = g_mdoff; n = ND; break;
    }
    int t = threadIdx.x;
    s[t] = (t < n) ? cnt[t] : 0;
    __syncthreads();
    for (int o = 1; o < 1024; o <<= 1) {
        int v = (t >= o) ? s[t - o] : 0;
        __syncthreads();
        s[t] += v;
        __syncthreads();
    }
    if (t < n) {
        off[t + 1] = s[t];
        if (t == 0) off[0] = 0;
        cnt[t] = 0;
    }
}

__global__ void csr_fill_kernel(const int* __restrict__ qsrc, const int* __restrict__ qdst, int EQ,
                                const int* __restrict__ dsrc, const int* __restrict__ ddst, int ED,
                                const int* __restrict__ qi, const int* __restrict__ di, int EM)
{
    int e = blockIdx.x * blockDim.x + threadIdx.x;
    if (e < EQ) {
        int d = qdst[e];
        g_qsrcs[g_qoff[d] + atomicAdd(&g_qcnt[d], 1)] = qsrc[e];
    } else if (e < EQ + ED) {
        int w = e - EQ;
        int d = ddst[w];
        g_dsrcs[g_doff[d] + atomicAdd(&g_dcnt[d], 1)] = dsrc[w];
    } else if (e < EQ + ED + EM) {
        int w = e - EQ - ED;
        int q = qi[w];
        g_mqe[g_mqoff[q] + atomicAdd(&g_mqcnt[q], 1)] = w;
    } else if (e < EQ + ED + 2 * EM) {
        int w = e - EQ - ED - EM;
        int d = di[w];
        g_mde[g_mdoff[d] + atomicAdd(&g_mdcnt[d], 1)] = w;
    }
}

// ---------------- HMMA split-bf16 GEMM, 64x64 tiles (R6, unchanged) ----------------
struct GemmJob {
    const float* A;
    const __nv_bfloat16* Bh;
    const __nv_bfloat16* Bl;
    float* C;
    const float* bias;
    int M, N, K, lda, ldc;
};

#define HG_A    0
#define HG_ASTR 288
#define HG_BH   18432
#define HG_BL   27648
#define HG_BSTR 144
#define HG_SMEM 36864

__global__ void __launch_bounds__(256, 2)
hgemm_kernel(GemmJob j0, GemmJob j1)
{
    GemmJob jb = (blockIdx.z == 0) ? j0 : j1;
    const int n0 = blockIdx.x * 64;
    const int m0 = blockIdx.y * 64;
    if (n0 >= jb.N || m0 >= jb.M) return;
    extern __shared__ char sm[];
    const int t = threadIdx.x, lane = t & 31, wid = t >> 5;
    const int warp_m = wid & 1, warp_n = wid >> 1;
    const int qr = lane >> 2, qk = (lane & 3) * 2;
    float acc[2][2][4] = {};

    for (int kc = 0; kc < jb.K; kc += 64) {
        __syncthreads();
        {
            int row = t >> 2, c4 = (t & 3) * 4;
            const float4* src = (const float4*)(jb.A + (size_t)(m0 + row) * jb.lda + kc) + c4;
            float4* dst = (float4*)(sm + HG_A + row * HG_ASTR + c4 * 16);
            #pragma unroll
            for (int i = 0; i < 4; i++) dst[i] = src[i];
        }
        #pragma unroll
        for (int p = 0; p < 2; p++) {
            int idx = t + p * 256;
            int row = idx >> 3, c = idx & 7;
            size_t go = (size_t)(n0 + row) * jb.K + kc + c * 8;
            *(uint4*)(sm + HG_BH + row * HG_BSTR + c * 16) = *(const uint4*)(jb.Bh + go);
            *(uint4*)(sm + HG_BL + row * HG_BSTR + c * 16) = *(const uint4*)(jb.Bl + go);
        }
        __syncthreads();
        #pragma unroll
        for (int kk = 0; kk < 64; kk += 16) {
            uint32_t bh[2][2], bl[2][2];
            #pragma unroll
            for (int f = 0; f < 2; f++) {
                int n = warp_n * 16 + f * 8 + qr;
                const char* bp = sm + n * HG_BSTR + (kk + qk) * 2;
                bh[f][0] = *(const uint32_t*)(bp + HG_BH);
                bh[f][1] = *(const uint32_t*)(bp + HG_BH + 16);
                bl[f][0] = *(const uint32_t*)(bp + HG_BL);
                bl[f][1] = *(const uint32_t*)(bp + HG_BL + 16);
            }
            #pragma unroll
            for (int s = 0; s < 2; s++) {
                int r = warp_m * 32 + s * 16 + qr;
                const char* ap = sm + HG_A + r * HG_ASTR + (kk + qk) * 4;
                float2 a0 = *(const float2*)ap;
                float2 a1 = *(const float2*)(ap + 8 * HG_ASTR);
                float2 a2 = *(const float2*)(ap + 32);
                float2 a3 = *(const float2*)(ap + 8 * HG_ASTR + 32);
                uint32_t ah[4], al[4];
                split_pack(a0.x, a0.y, ah[0], al[0]);
                split_pack(a1.x, a1.y, ah[1], al[1]);
                split_pack(a2.x, a2.y, ah[2], al[2]);
                split_pack(a3.x, a3.y, ah[3], al[3]);
                #pragma unroll
                for (int f = 0; f < 2; f++) {
                    mma_bf16(acc[s][f], ah[0], ah[1], ah[2], ah[3], bh[f][0], bh[f][1]);
                    mma_bf16(acc[s][f], al[0], al[1], al[2], al[3], bh[f][0], bh[f][1]);
                    mma_bf16(acc[s][f], ah[0], ah[1], ah[2], ah[3], bl[f][0], bl[f][1]);
                }
            }
        }
    }
    #pragma unroll
    for (int s = 0; s < 2; s++) {
        int r = m0 + warp_m * 32 + s * 16 + qr;
        #pragma unroll
        for (int f = 0; f < 2; f++) {
            int n = n0 + warp_n * 16 + f * 8 + qk;
            float bs0 = jb.bias ? jb.bias[n] : 0.0f;
            float bs1 = jb.bias ? jb.bias[n + 1] : 0.0f;
            float2 v0 = { acc[s][f][0] + bs0, acc[s][f][1] + bs1 };
            float2 v1 = { acc[s][f][2] + bs0, acc[s][f][3] + bs1 };
            *(float2*)(jb.C + (size_t)r * jb.ldc + n) = v0;
            *(float2*)(jb.C + (size_t)(r + 8) * jb.ldc + n) = v1;
        }
    }
}

// ---------------- fused GCN gather: self + edge-agg + bias + relu, zero right half ----
__global__ void gcn_gather_kernel(const float* __restrict__ qh, const float* __restrict__ dh,
                                  const float* __restrict__ qb, const float* __restrict__ db,
                                  float* __restrict__ qout, float* __restrict__ dout)
{
    const float4 z4 = {0.f, 0.f, 0.f, 0.f};
    int v = blockIdx.x * blockDim.x + threadIdx.x;
    const float* h; const float* b; float* out;
    const int* off; const int* srcs; int node;
    if (v < NQ * 64) {
        node = v >> 6; h = qh; b = qb; out = qout; off = g_qoff; srcs = g_qsrcs;
    } else if (v < (NQ + ND) * 64) {
        v -= NQ * 64;
        node = v >> 6; h = dh; b = db; out = dout; off = g_doff; srcs = g_dsrcs;
    } else return;
    int c = v & 63;
    int lo = off[node], hi = off[node + 1];
    float degd = (float)(hi - lo) + 1.0f;
    float rsd = rsqrtf(degd);
    float invd = 1.0f / degd;
    float4 hh = ((const float4*)h)[node * 64 + c];
    float4 bb = ((const float4*)b)[c];
    float4 acc = { hh.x * invd + bb.x, hh.y * invd + bb.y,
                   hh.z * invd + bb.z, hh.w * invd + bb.w };
    for (int k = lo; k < hi; k++) {
        int s = srcs[k];
        float degs = (float)(off[s + 1] - off[s]) + 1.0f;
        float coef = rsqrtf(degs) * rsd;
        float4 hs = ((const float4*)h)[s * 64 + c];
        acc.x += coef * hs.x; acc.y += coef * hs.y;
        acc.z += coef * hs.z; acc.w += coef * hs.w;
    }
    acc.x = fmaxf(acc.x, 0.f); acc.y = fmaxf(acc.y, 0.f);
    acc.z = fmaxf(acc.z, 0.f); acc.w = fmaxf(acc.w, 0.f);
    ((float4*)out)[node * 128 + c] = acc;
    ((float4*)out)[node * 128 + 64 + c] = z4;
}

// ---------------- cross-matching kernels ----------------
__global__ void cos_norm_kernel(const int* __restrict__ qi, const int* __restrict__ di, int E,
                                const float* __restrict__ qbuf, const float* __restrict__ dbuf,
                                float* __restrict__ cosw)
{
    int e = blockIdx.x * (blockDim.x >> 5) + (threadIdx.x >> 5);
    int lane = threadIdx.x & 31;
    if (e >= E) return;
    const float* qp = qbuf + qi[e] * CAT;
    const float* dp = dbuf + di[e] * CAT;
    float qq = 0.f, dd = 0.f, qd = 0.f;
    for (int k = lane; k < DD; k += 32) {
        float a = qp[k], b = dp[k];
        qq += a * a; dd += b * b; qd += a * b;
    }
    #pragma unroll
    for (int o = 16; o; o >>= 1) {
        qq += __shfl_xor_sync(0xFFFFFFFFu, qq, o);
        dd += __shfl_xor_sync(0xFFFFFFFFu, dd, o);
        qd += __shfl_xor_sync(0xFFFFFFFFu, qd, o);
    }
    if (lane == 0)
        cosw[e] = qd / (fmaxf(sqrtf(qq), 1e-8f) * fmaxf(sqrtf(dd), 1e-8f));
}

__global__ void softmax_kernel(float* __restrict__ cosw, int E)
{
    __shared__ float red[1024];
    int t = threadIdx.x;
    float m = -1e30f;
    for (int e = t; e < E; e += 1024) m = fmaxf(m, cosw[e]);
    red[t] = m; __syncthreads();
    for (int s = 512; s; s >>= 1) { if (t < s) red[t] = fmaxf(red[t], red[t + s]); __syncthreads(); }
    float mx = red[0]; __syncthreads();
    float sum = 0.f;
    for (int e = t; e < E; e += 1024) sum += expf(cosw[e] - mx);
    red[t] = sum; __syncthreads();
    for (int s = 512; s; s >>= 1) { if (t < s) red[t] += red[t + s]; __syncthreads(); }
    float inv = 1.0f / red[0];
    for (int e = t; e < E; e += 1024) cosw[e] = expf(cosw[e] - mx) * inv;
}

// gather both sides of the cross aggregation: reads LEFT halves, writes RIGHT halves
__global__ void cross_gather_kernel(const int* __restrict__ qi, const int* __restrict__ di,
                                    float* __restrict__ qbuf, float* __restrict__ dbuf,
                                    const float* __restrict__ w)
{
    int v = blockIdx.x * blockDim.x + threadIdx.x;
    if (v < NQ * 64) {
        int q = v >> 6, c = v & 63;
        float4 acc = {0.f, 0.f, 0.f, 0.f};
        int lo = g_mqoff[q], hi = g_mqoff[q + 1];
        for (int k = lo; k < hi; k++) {
            int e = g_mqe[k];
            float we = w[e];
            float4 dv = ((const float4*)dbuf)[di[e] * 128 + c];
            acc.x += we * dv.x; acc.y += we * dv.y;
            acc.z += we * dv.z; acc.w += we * dv.w;
        }
        ((float4*)qbuf)[q * 128 + 64 + c] = acc;
    } else if (v < (NQ + ND) * 64) {
        v -= NQ * 64;
        int d = v >> 6, c = v & 63;
        float4 acc = {0.f, 0.f, 0.f, 0.f};
        int lo = g_mdoff[d], hi = g_mdoff[d + 1];
        for (int k = lo; k < hi; k++) {
            int e = g_mde[k];
            float we = w[e];
            float4 qv = ((const float4*)qbuf)[qi[e] * 128 + c];
            acc.x += we * qv.x; acc.y += we * qv.y;
            acc.z += we * qv.z; acc.w += we * qv.w;
        }
        ((float4*)dbuf)[d * 128 + 64 + c] = acc;
    }
}

// ---------------- HMMA pair-MLP kernel (unchanged) ----------------
#define SM_BQ   0
#define SM_B3   1024
#define SM_W4   1536
#define SM_RED  2048
#define SM_BD   4096
#define BD_STR  1032
#define SM_W3H  (SM_BD + 64 * BD_STR)
#define W3_STR  528
#define SM_W3L  (SM_W3H + 128 * W3_STR)
#define SM_PAIR_TOTAL (SM_W3L + 128 * W3_STR)

__global__ void __launch_bounds__(512, 1)
pair_hmma_kernel(const float* __restrict__ Bq, const float* __restrict__ Bd,
                 const __nv_bfloat16* __restrict__ w3hi, const __nv_bfloat16* __restrict__ w3lo,
                 const float* __restrict__ b3, const float* __restrict__ w4,
                 const float* __restrict__ b4, float* __restrict__ pred)
{
    extern __shared__ char smem[];
    const int t = threadIdx.x, lane = t & 31, wid = t >> 5;
    const int warp_m = wid & 3, warp_n = wid >> 2;
    const int j0 = blockIdx.x * 64;
    const int i0 = blockIdx.y * 8;

    for (int v = t; v < 64 * 128; v += 512) {
        int row = v >> 7, c = v & 127;
        *(float2*)(smem + SM_BD + row * BD_STR + c * 8) =
            ((const float2*)(Bd + (size_t)(j0 + row) * DD))[c];
    }
    for (int v = t; v < 128 * 32; v += 512) {
        int row = v >> 5, c = v & 31;
        *(uint4*)(smem + SM_W3H + row * W3_STR + c * 16) =
            ((const uint4*)(w3hi + (size_t)row * DD))[c];
        *(uint4*)(smem + SM_W3L + row * W3_STR + c * 16) =
            ((const uint4*)(w3lo + (size_t)row * DD))[c];
    }
    if (t < 32) ((uint4*)(smem + SM_B3))[t] = ((const uint4*)b3)[t];
    else if (t < 64) ((uint4*)(smem + SM_W4))[t - 32] = ((const uint4*)w4)[t - 32];
    const float b4v = b4[0];

    const float* b3s = (const float*)(smem + SM_B3);
    const float* w4s = (const float*)(smem + SM_W4);
    float* red = (float*)(smem + SM_RED);

    const int r_lo = warp_m * 16 + (lane >> 2);
    const char* bd_lo = smem + SM_BD + r_lo * BD_STR;
    const char* bd_hi = bd_lo + 8 * BD_STR;
    const int kq = (lane & 3) * 2;
    const int nrow = warp_n * 32 + (lane >> 2);

    for (int il = 0; il < 8; il++) {
        __syncthreads();
        if (t < 64) ((uint4*)(smem + SM_BQ))[t] = ((const uint4*)(Bq + (size_t)(i0 + il) * DD))[t];
        __syncthreads();

        float c[4][4];
        #pragma unroll
        for (int nt = 0; nt < 4; nt++)
            #pragma unroll
            for (int u = 0; u < 4; u++) c[nt][u] = 0.0f;

        #pragma unroll
        for (int ks = 0; ks < 16; ks++) {
            const int kb = ks * 16 + kq;
            float2 q0 = *(const float2*)(smem + SM_BQ + kb * 4);
            float2 q1 = *(const float2*)(smem + SM_BQ + (kb + 8) * 4);
            uint32_t ah[4], al[4];
            {
                float2 d = *(const float2*)(bd_lo + kb * 4);
                split_pack(fmaxf(d.x + q0.x, 0.0f), fmaxf(d.y + q0.y, 0.0f), ah[0], al[0]);
            }
            {
                float2 d = *(const float2*)(bd_hi + kb * 4);
                split_pack(fmaxf(d.x + q0.x, 0.0f), fmaxf(d.y + q0.y, 0.0f), ah[1], al[1]);
            }
            {
                float2 d = *(const float2*)(bd_lo + (kb + 8) * 4);
                split_pack(fmaxf(d.x + q1.x, 0.0f), fmaxf(d.y + q1.y, 0.0f), ah[2], al[2]);
            }
            {
                float2 d = *(const float2*)(bd_hi + (kb + 8) * 4);
                split_pack(fmaxf(d.x + q1.x, 0.0f), fmaxf(d.y + q1.y, 0.0f), ah[3], al[3]);
            }
            #pragma unroll
            for (int nt = 0; nt < 4; nt++) {
                const int roff = (nrow + nt * 8) * W3_STR + kb * 2;
                uint32_t bh0 = *(const uint32_t*)(smem + SM_W3H + roff);
                uint32_t bh1 = *(const uint32_t*)(smem + SM_W3H + roff + 16);
                uint32_t bl0 = *(const uint32_t*)(smem + SM_W3L + roff);
                uint32_t bl1 = *(const uint32_t*)(smem + SM_W3L + roff + 16);
                mma_bf16(c[nt], ah[0], ah[1], ah[2], ah[3], bh0, bh1);
                mma_bf16(c[nt], al[0], al[1], al[2], al[3], bh0, bh1);
                mma_bf16(c[nt], ah[0], ah[1], ah[2], ah[3], bl0, bl1);
            }
        }

        float s_lo = 0.0f, s_hi = 0.0f;
        #pragma unroll
        for (int nt = 0; nt < 4; nt++) {
            int n0 = warp_n * 32 + nt * 8 + (lane & 3) * 2;
            float b30 = b3s[n0], b31 = b3s[n0 + 1];
            float w40 = w4s[n0], w41 = w4s[n0 + 1];
            s_lo += fmaxf(c[nt][0] + b30, 0.0f) * w40 + fmaxf(c[nt][1] + b31, 0.0f) * w41;
            s_hi += fmaxf(c[nt][2] + b30, 0.0f) * w40 + fmaxf(c[nt][3] + b31, 0.0f) * w41;
        }
        s_lo += __shfl_xor_sync(0xFFFFFFFFu, s_lo, 1);
        s_lo += __shfl_xor_sync(0xFFFFFFFFu, s_lo, 2);
        s_hi += __shfl_xor_sync(0xFFFFFFFFu, s_hi, 1);
        s_hi += __shfl_xor_sync(0xFFFFFFFFu, s_hi, 2);
        if ((lane & 3) == 0) {
            red[r_lo * 4 + warp_n] = s_lo;
            red[(r_lo + 8) * 4 + warp_n] = s_hi;
        }
        __syncthreads();
        if (t < 64) {
            float v = red[t * 4] + red[t * 4 + 1] + red[t * 4 + 2] + red[t * 4 + 3] + b4v;
            v = v > 0.0f ? v : 0.0f;
            pred[(size_t)(i0 + il) * ND + j0 + t] = v;
        }
    }
}

// ---------------- host orchestration ----------------
extern "C" void kernel_launch(void* const* d_in, const int* in_sizes, int n_in,
                              void* d_out, int out_size)
{
    const float* qfeat = (const float*)d_in[0];
    const float* dfeat = (const float*)d_in[1];
    const int*   qe    = (const int*)d_in[2];
    const int*   de    = (const int*)d_in[3];
    const int*   qi    = (const int*)d_in[4];
    const int*   di    = (const int*)d_in[5];
    const float* q_w0 = (const float*)d_in[6];
    const float* q_b0 = (const float*)d_in[7];
    const float* q_w1 = (const float*)d_in[8];
    const float* q_b1 = (const float*)d_in[9];
    const float* d_w0 = (const float*)d_in[10];
    const float* d_b0 = (const float*)d_in[11];
    const float* d_w1 = (const float*)d_in[12];
    const float* d_b1 = (const float*)d_in[13];
    const float* w1 = (const float*)d_in[14];
    const float* b1 = (const float*)d_in[15];
    const float* w2 = (const float*)d_in[16];
    const float* b2 = (const float*)d_in[17];
    const float* w3 = (const float*)d_in[18];
    const float* b3 = (const float*)d_in[19];
    const float* w4 = (const float*)d_in[20];
    const float* b4 = (const float*)d_in[21];

    const int EQ = in_sizes[2] / 2;
    const int ED = in_sizes[3] / 2;
    const int EM = in_sizes[4];

    float *qh, *dh, *qB, *dB, *cosw, *Bqp, *Bdp;
    __nv_bfloat16 *wh, *wl;
    cudaGetSymbolAddress((void**)&qh, g_qh);
    cudaGetSymbolAddress((void**)&dh, g_dh);
    cudaGetSymbolAddress((void**)&qB, g_qB);
    cudaGetSymbolAddress((void**)&dB, g_dB);
    cudaGetSymbolAddress((void**)&cosw, g_cosw);
    cudaGetSymbolAddress((void**)&Bqp, g_Bq);
    cudaGetSymbolAddress((void**)&Bdp, g_Bd);
    cudaGetSymbolAddress((void**)&wh, g_wh);
    cudaGetSymbolAddress((void**)&wl, g_wl);

    float* out = (float*)d_out;
    float* qOut = out + NQ * ND;
    float* dOut = qOut + NQ * CAT;

    cudaFuncSetAttribute(hgemm_kernel, cudaFuncAttributeMaxDynamicSharedMemorySize, HG_SMEM);
    cudaFuncSetAttribute(pair_hmma_kernel, cudaFuncAttributeMaxDynamicSharedMemorySize,
                         SM_PAIR_TOTAL);

    // ---- 1. pack all weights ----
    PackArgs pa;
    pa.j[0] = { q_w0,               DD,  DD,  DD,  OFF_QW0 };
    pa.j[1] = { d_w0,               DD,  DD,  DD,  OFF_DW0 };
    pa.j[2] = { q_w1,               CAT, DD,  DD,  OFF_QW1 };
    pa.j[3] = { d_w1,               CAT, DD,  DD,  OFF_DW1 };
    pa.j[4] = { w1,                 CAT, CAT, CAT, OFF_W1T };
    pa.j[5] = { w1 + CAT * CAT,     CAT, CAT, CAT, OFF_W1B };
    pa.j[6] = { w2,                 CAT, DD,  DD,  OFF_W2  };
    pa.j[7] = { w3,                 DD,  128, 128, OFF_W3  };
    pack_kernel<<<dim3(256, 8), 256>>>(pa, wh, wl);

    // ---- 2. CSR build (once) ----
    const int totE = EQ + ED + 2 * EM;
    csr_zero_kernel<<<4, 256>>>();
    csr_count_kernel<<<(totE + 255) / 256, 256>>>(qe + EQ, EQ, de + ED, ED, qi, di, EM);
    csr_scan_kernel<<<4, 1024>>>();
    csr_fill_kernel<<<(totE + 255) / 256, 256>>>(qe, qe + EQ, EQ, de, de + ED, ED, qi, di, EM);

    const int nodeBlocks = (NQ + ND) * 64 / 256;

    // ---- 3. layer 0 ----
    {
        GemmJob jq = { qfeat, wh + OFF_QW0, wl + OFF_QW0, qh, nullptr, NQ, DD, DD, DD, DD };
        GemmJob jd = { dfeat, wh + OFF_DW0, wl + OFF_DW0, dh, nullptr, ND, DD, DD, DD, DD };
        hgemm_kernel<<<dim3(DD / 64, ND / 64, 2), 256, HG_SMEM>>>(jq, jd);
    }
    gcn_gather_kernel<<<nodeBlocks, 256>>>(qh, dh, q_b0, d_b0, qB, dB);
    cos_norm_kernel<<<(EM + 7) / 8, 256>>>(qi, di, EM, qB, dB, cosw);
    softmax_kernel<<<1, 1024>>>(cosw, EM);
    cross_gather_kernel<<<nodeBlocks, 256>>>(qi, di, qB, dB, cosw);

    // ---- 4. layer 1 (outputs straight into d_out) ----
    {
        GemmJob jq = { qB, wh + OFF_QW1, wl + OFF_QW1, qh, nullptr, NQ, DD, CAT, CAT, DD };
        GemmJob jd = { dB, wh + OFF_DW1, wl + OFF_DW1, dh, nullptr, ND, DD, CAT, CAT, DD };
        hgemm_kernel<<<dim3(DD / 64, ND / 64, 2), 256, HG_SMEM>>>(jq, jd);
    }
    gcn_gather_kernel<<<nodeBlocks, 256>>>(qh, dh, q_b1, d_b1, qOut, dOut);
    cos_norm_kernel<<<(EM + 7) / 8, 256>>>(qi, di, EM, qOut, dOut, cosw);
    softmax_kernel<<<1, 1024>>>(cosw, EM);
    cross_gather_kernel<<<nodeBlocks, 256>>>(qi, di, qOut, dOut, cosw);

    // ---- 5. final scoring (w1/w2 folded) ----
    {
        GemmJob jq = { qOut, wh + OFF_W1T, wl + OFF_W1T, qB, b1, NQ, CAT, CAT, CAT, CAT };
        GemmJob jd = { dOut, wh + OFF_W1B, wl + OFF_W1B, dB, nullptr, ND, CAT, CAT, CAT, CAT };
        hgemm_kernel<<<dim3(CAT / 64, ND / 64, 2), 256, HG_SMEM>>>(jq, jd);
    }
    {
        GemmJob jq = { qB, wh + OFF_W2, wl + OFF_W2, Bqp, b2, NQ, DD, CAT, CAT, DD };
        GemmJob jd = { dB, wh + OFF_W2, wl + OFF_W2, Bdp, nullptr, ND, DD, CAT, CAT, DD };
        hgemm_kernel<<<dim3(DD / 64, ND / 64, 2), 256, HG_SMEM>>>(jq, jd);
    }

    // ---- 6. pair MLP -> pred ----
    dim3 pg(ND / 64, NQ / 8);
    pair_hmma_kernel<<<pg, 512, SM_PAIR_TOTAL>>>(Bqp, Bdp, wh + OFF_W3, wl + OFF_W3,
                                                 b3, w4, b4, out);
}